// round 13
// baseline (speedup 1.0000x reference)
#include <cuda_runtime.h>
#include <cuda_fp16.h>
#include <cuda_bf16.h>
#include <cstdint>

// CustomRotatedRoIAlign:
//   Pass 1: transpose fm (B,C,H,W) fp32 -> g_fm_h (B,H,W,C') fp16 with
//           permuted channel axis: slot 8q+i holds channel 32*i+q (q<32,i<8).
//           fm reads via __ldcs (streamed once, don't evict scratch from L2).
//   Pass 2: one CTA (512 thr, 4 CTAs/SM) per box; 16B channel gathers
//           (L2-resident scratch); half2 accumulation; conflict-free fp32
//           staging; single cp.async.bulk smem->gmem writeout (no per-thread
//           LDS/STG in the epilogue).

#define RR_B 2
#define RR_C 256
#define RR_H 200
#define RR_W 304
#define RR_HW (RR_H * RR_W)
#define RR_N 512
#define OUT_H 7
#define OUT_W 7
#define NPTS (OUT_H * OUT_W)
#define OUT_BYTES (RR_C * NPTS * 4)        // 50176 B per box

// 2*60800*256 halves = 62.3 MB scratch (fits in 126MB L2)
__device__ __half g_fm_h[(size_t)RR_B * RR_HW * RR_C];

// ---------------------------------------------------------------------------
// Pass 1: transpose+permute. Tile: 32 channel-rows x 128 hw, 17KB smem.
// Row r = 4i+j holds channel 32i + q0 + j (q0 = 4*blockIdx.y, j<4, i<8).
// ---------------------------------------------------------------------------
__global__ __launch_bounds__(256)
void rroi_transpose_kernel(const float* __restrict__ fm)
{
    __shared__ float tile[32][133];

    const int b   = blockIdx.z;
    const int q0  = blockIdx.y * 4;
    const int hw0 = blockIdx.x * 128;
    const int t   = threadIdx.x;

    // Load phase (streaming reads: used exactly once)
    {
        const int r  = t >> 3;                         // tile row 0..31
        const int ch = 32 * (r >> 2) + q0 + (r & 3);   // channel for this row
        const int h4 = (t & 7) * 4;
        const float* src = fm + ((size_t)b * RR_C + ch) * RR_HW + hw0;
        #pragma unroll
        for (int j = 0; j < 4; j++) {
            const float4 v = __ldcs((const float4*)(src + h4 + 32 * j));
            float* tp = &tile[r][h4 + 32 * j];
            tp[0] = v.x; tp[1] = v.y; tp[2] = v.z; tp[3] = v.w;
        }
    }
    __syncthreads();

    // Store phase: thread (qj = t&3, hwr = t>>2), 2 hw chunks of 64.
    // Slot 8(q0+qj)+i <- channel 32i + q0 + qj  (tile row 4i+qj).
    {
        const int qj  = t & 3;
        const int hwr = t >> 2;              // 0..63
        __half* dst = g_fm_h + ((size_t)(b * RR_HW + hw0)) * RR_C + 8 * (q0 + qj);
        #pragma unroll
        for (int k = 0; k < 2; k++) {
            const int hw = hwr + 64 * k;
            const __half2 h0 = __floats2half2_rn(tile[qj     ][hw], tile[qj + 4 ][hw]);
            const __half2 h1 = __floats2half2_rn(tile[qj + 8 ][hw], tile[qj + 12][hw]);
            const __half2 h2 = __floats2half2_rn(tile[qj + 16][hw], tile[qj + 20][hw]);
            const __half2 h3 = __floats2half2_rn(tile[qj + 24][hw], tile[qj + 28][hw]);
            uint4 pk;
            pk.x = *(const unsigned int*)&h0;
            pk.y = *(const unsigned int*)&h1;
            pk.z = *(const unsigned int*)&h2;
            pk.w = *(const unsigned int*)&h3;
            *(uint4*)(dst + (size_t)hw * RR_C) = pk;
        }
    }
}

// ---------------------------------------------------------------------------
// Pass 2: sampling. One CTA per (b,n), 512 threads, 4 CTAs/SM.
// Thread = (q = tid&31, pg = tid>>5 in 0..15). Point p = 16j+pg, j = 0..3;
// half2 accumulation of the 4 bilinear corners, fp32 staging to smem,
// bulk-async epilogue.
// ---------------------------------------------------------------------------
__global__ __launch_bounds__(512, 4)
void rroi_sample_kernel(const float* __restrict__ boxes,
                        float* __restrict__ out)
{
    extern __shared__ float s_out[];      // RR_C * NPTS floats, rows of 49

    __shared__ int   s_off[4][NPTS];      // (y*W+x)*C half-offsets
    __shared__ float s_w[4][NPTS];

    const int bn  = blockIdx.x;
    const int b   = bn / RR_N;
    const int tid = threadIdx.x;

    if (tid < NPTS) {
        const float* bx = boxes + (size_t)bn * 5;
        const float cx  = bx[0];
        const float cy  = bx[1];
        const float w   = bx[2];
        const float h   = bx[3];
        const float ang = bx[4];

        const float rad = -ang * (3.14159265358979323846f / 180.0f);
        float ss, cc;
        sincosf(rad, &ss, &cc);

        const float a00 =  (w / (float)RR_W) * cc;
        const float a01 = -(h / (float)RR_H) * ss;
        const float a02 =  2.0f * cx / (float)RR_W - 1.0f;
        const float a10 =  (w / (float)RR_W) * ss;
        const float a11 =  (h / (float)RR_H) * cc;
        const float a12 =  2.0f * cy / (float)RR_H - 1.0f;

        const int oy = tid / OUT_W;
        const int ox = tid - oy * OUT_W;
        const float xs = (2.0f * (float)ox + 1.0f) / (float)OUT_W - 1.0f;
        const float ys = (2.0f * (float)oy + 1.0f) / (float)OUT_H - 1.0f;

        const float gx = a00 * xs + a01 * ys + a02;
        const float gy = a10 * xs + a11 * ys + a12;

        const float ix = ((gx + 1.0f) * (float)RR_W - 1.0f) * 0.5f;
        const float iy = ((gy + 1.0f) * (float)RR_H - 1.0f) * 0.5f;

        const float x0 = floorf(ix);
        const float y0 = floorf(iy);
        const float wx1 = ix - x0;
        const float wy1 = iy - y0;

        #pragma unroll
        for (int k = 0; k < 4; k++) {
            const float xc = x0 + (float)(k & 1);
            const float yc = y0 + (float)(k >> 1);
            const float wgt = ((k & 1)  ? wx1 : (1.0f - wx1)) *
                              ((k >> 1) ? wy1 : (1.0f - wy1));
            const bool valid = (xc >= 0.0f) && (xc <= (float)(RR_W - 1)) &&
                               (yc >= 0.0f) && (yc <= (float)(RR_H - 1));
            const float xcl = fminf(fmaxf(xc, 0.0f), (float)(RR_W - 1));
            const float ycl = fminf(fmaxf(yc, 0.0f), (float)(RR_H - 1));
            const int xi = (int)xcl;
            const int yi = (int)ycl;
            s_off[k][tid] = (yi * RR_W + xi) * RR_C;
            s_w[k][tid]   = valid ? wgt : 0.0f;
        }
    }
    __syncthreads();

    const int q  = tid & 31;              // slot octet -> channels q+32i
    const int pg = tid >> 5;              // 0..15 point group
    const __half* __restrict__ base =
        g_fm_h + (size_t)b * RR_HW * RR_C + 8 * q;

    #pragma unroll
    for (int j = 0; j < 4; j++) {
        const int p  = 16 * j + pg;
        const int pi = min(p, NPTS - 1);

        const uint4 u0 = *(const uint4*)(base + s_off[0][pi]);
        const uint4 u1 = *(const uint4*)(base + s_off[1][pi]);
        const uint4 u2 = *(const uint4*)(base + s_off[2][pi]);
        const uint4 u3 = *(const uint4*)(base + s_off[3][pi]);

        const __half2 W0 = __float2half2_rn(s_w[0][pi]);
        const __half2 W1 = __float2half2_rn(s_w[1][pi]);
        const __half2 W2 = __float2half2_rn(s_w[2][pi]);
        const __half2 W3 = __float2half2_rn(s_w[3][pi]);

        // half2 4-corner accumulation; pairs = channels (q+64m, q+32+64m)
        __half2 h0 = __hmul2(W0, *(const __half2*)&u0.x);
        h0 = __hfma2(W1, *(const __half2*)&u1.x, h0);
        h0 = __hfma2(W2, *(const __half2*)&u2.x, h0);
        h0 = __hfma2(W3, *(const __half2*)&u3.x, h0);

        __half2 h1 = __hmul2(W0, *(const __half2*)&u0.y);
        h1 = __hfma2(W1, *(const __half2*)&u1.y, h1);
        h1 = __hfma2(W2, *(const __half2*)&u2.y, h1);
        h1 = __hfma2(W3, *(const __half2*)&u3.y, h1);

        __half2 h2 = __hmul2(W0, *(const __half2*)&u0.z);
        h2 = __hfma2(W1, *(const __half2*)&u1.z, h2);
        h2 = __hfma2(W2, *(const __half2*)&u2.z, h2);
        h2 = __hfma2(W3, *(const __half2*)&u3.z, h2);

        __half2 h3 = __hmul2(W0, *(const __half2*)&u0.w);
        h3 = __hfma2(W1, *(const __half2*)&u1.w, h3);
        h3 = __hfma2(W2, *(const __half2*)&u2.w, h3);
        h3 = __hfma2(W3, *(const __half2*)&u3.w, h3);

        if (p < NPTS) {
            const float2 f0 = __half22float2(h0);
            const float2 f1 = __half22float2(h1);
            const float2 f2 = __half22float2(h2);
            const float2 f3 = __half22float2(h3);
            // slot 8q+i is channel 32i+q; lane delta = 49 words (odd)
            // -> conflict-free scalar STS
            s_out[(q       ) * NPTS + p] = f0.x;
            s_out[(q + 32  ) * NPTS + p] = f0.y;
            s_out[(q + 64  ) * NPTS + p] = f1.x;
            s_out[(q + 96  ) * NPTS + p] = f1.y;
            s_out[(q + 128 ) * NPTS + p] = f2.x;
            s_out[(q + 160 ) * NPTS + p] = f2.y;
            s_out[(q + 192 ) * NPTS + p] = f3.x;
            s_out[(q + 224 ) * NPTS + p] = f3.y;
        }
    }
    __syncthreads();

    // Bulk async epilogue: one 50176B smem -> gmem copy (TMA engine), no
    // per-thread LDS/STG. fence orders the generic-proxy STS above against
    // the async proxy; issuing thread waits for read-completion before exit.
    if (tid == 0) {
        float* dst = out + (size_t)bn * RR_C * NPTS;
        uint32_t saddr;
        asm volatile("{ .reg .u64 t; cvta.to.shared.u64 t, %1; cvt.u32.u64 %0, t; }"
                     : "=r"(saddr) : "l"(s_out));
        asm volatile("fence.proxy.async.shared::cta;" ::: "memory");
        asm volatile("cp.async.bulk.global.shared::cta.bulk_group [%0], [%1], %2;"
                     :: "l"(dst), "r"(saddr), "n"(OUT_BYTES) : "memory");
        asm volatile("cp.async.bulk.commit_group;" ::: "memory");
        asm volatile("cp.async.bulk.wait_group.read 0;" ::: "memory");
    }
}

// ---------------------------------------------------------------------------

extern "C" void kernel_launch(void* const* d_in, const int* in_sizes, int n_in,
                              void* d_out, int out_size)
{
    const float* fm    = (const float*)d_in[0];
    const float* boxes = (const float*)d_in[1];
    float* out         = (float*)d_out;

    static int smem_set = 0;
    if (!smem_set) {
        cudaFuncSetAttribute(rroi_sample_kernel,
                             cudaFuncAttributeMaxDynamicSharedMemorySize,
                             RR_C * NPTS * (int)sizeof(float));
        smem_set = 1;
    }

    dim3 tgrid(RR_HW / 128, RR_C / 32, RR_B);
    rroi_transpose_kernel<<<tgrid, 256>>>(fm);

    rroi_sample_kernel<<<RR_B * RR_N, 512, RR_C * NPTS * (int)sizeof(float)>>>(boxes, out);
}

// round 14
// speedup vs baseline: 1.1116x; 1.1116x over previous
#include <cuda_runtime.h>
#include <cuda_fp16.h>
#include <cuda_bf16.h>
#include <cstdint>

// CustomRotatedRoIAlign:
//   Pass 1: transpose fm (B,C,H,W) fp32 -> g_fm_h (B,H,W,C') fp16 with
//           permuted channel axis: slot 8q+i holds channel 32*i+q (q<32,i<8).
//           fm reads via __ldcs (streamed once, don't evict scratch from L2).
//   Pass 2: one CTA (512 thr, 4 CTAs/SM) per box; 16B channel gathers
//           (L2-resident scratch); half2 accumulation; conflict-free fp32
//           staging; single cp.async.bulk smem->gmem writeout with
//           L2::evict_first policy (out is never re-read; keeps L2 clean
//           for the next graph replay's transpose).

#define RR_B 2
#define RR_C 256
#define RR_H 200
#define RR_W 304
#define RR_HW (RR_H * RR_W)
#define RR_N 512
#define OUT_H 7
#define OUT_W 7
#define NPTS (OUT_H * OUT_W)
#define OUT_BYTES (RR_C * NPTS * 4)        // 50176 B per box

// 2*60800*256 halves = 62.3 MB scratch (fits in 126MB L2)
__device__ __half g_fm_h[(size_t)RR_B * RR_HW * RR_C];

// ---------------------------------------------------------------------------
// Pass 1: transpose+permute. Tile: 32 channel-rows x 128 hw, 17KB smem.
// Row r = 4i+j holds channel 32i + q0 + j (q0 = 4*blockIdx.y, j<4, i<8).
// ---------------------------------------------------------------------------
__global__ __launch_bounds__(256)
void rroi_transpose_kernel(const float* __restrict__ fm)
{
    __shared__ float tile[32][133];

    const int b   = blockIdx.z;
    const int q0  = blockIdx.y * 4;
    const int hw0 = blockIdx.x * 128;
    const int t   = threadIdx.x;

    // Load phase (streaming reads: used exactly once)
    {
        const int r  = t >> 3;                         // tile row 0..31
        const int ch = 32 * (r >> 2) + q0 + (r & 3);   // channel for this row
        const int h4 = (t & 7) * 4;
        const float* src = fm + ((size_t)b * RR_C + ch) * RR_HW + hw0;
        #pragma unroll
        for (int j = 0; j < 4; j++) {
            const float4 v = __ldcs((const float4*)(src + h4 + 32 * j));
            float* tp = &tile[r][h4 + 32 * j];
            tp[0] = v.x; tp[1] = v.y; tp[2] = v.z; tp[3] = v.w;
        }
    }
    __syncthreads();

    // Store phase: thread (qj = t&3, hwr = t>>2), 2 hw chunks of 64.
    // Slot 8(q0+qj)+i <- channel 32i + q0 + qj  (tile row 4i+qj).
    {
        const int qj  = t & 3;
        const int hwr = t >> 2;              // 0..63
        __half* dst = g_fm_h + ((size_t)(b * RR_HW + hw0)) * RR_C + 8 * (q0 + qj);
        #pragma unroll
        for (int k = 0; k < 2; k++) {
            const int hw = hwr + 64 * k;
            const __half2 h0 = __floats2half2_rn(tile[qj     ][hw], tile[qj + 4 ][hw]);
            const __half2 h1 = __floats2half2_rn(tile[qj + 8 ][hw], tile[qj + 12][hw]);
            const __half2 h2 = __floats2half2_rn(tile[qj + 16][hw], tile[qj + 20][hw]);
            const __half2 h3 = __floats2half2_rn(tile[qj + 24][hw], tile[qj + 28][hw]);
            uint4 pk;
            pk.x = *(const unsigned int*)&h0;
            pk.y = *(const unsigned int*)&h1;
            pk.z = *(const unsigned int*)&h2;
            pk.w = *(const unsigned int*)&h3;
            *(uint4*)(dst + (size_t)hw * RR_C) = pk;
        }
    }
}

// ---------------------------------------------------------------------------
// Pass 2: sampling. One CTA per (b,n), 512 threads, 4 CTAs/SM.
// Thread = (q = tid&31, pg = tid>>5 in 0..15). Point p = 16j+pg, j = 0..3;
// half2 accumulation of the 4 bilinear corners, fp32 staging to smem,
// bulk-async evict-first epilogue.
// ---------------------------------------------------------------------------
__global__ __launch_bounds__(512, 4)
void rroi_sample_kernel(const float* __restrict__ boxes,
                        float* __restrict__ out)
{
    extern __shared__ float s_out[];      // RR_C * NPTS floats, rows of 49

    __shared__ int   s_off[4][NPTS];      // (y*W+x)*C half-offsets
    __shared__ float s_w[4][NPTS];

    const int bn  = blockIdx.x;
    const int b   = bn / RR_N;
    const int tid = threadIdx.x;

    if (tid < NPTS) {
        const float* bx = boxes + (size_t)bn * 5;
        const float cx  = bx[0];
        const float cy  = bx[1];
        const float w   = bx[2];
        const float h   = bx[3];
        const float ang = bx[4];

        const float rad = -ang * (3.14159265358979323846f / 180.0f);
        float ss, cc;
        sincosf(rad, &ss, &cc);

        const float a00 =  (w / (float)RR_W) * cc;
        const float a01 = -(h / (float)RR_H) * ss;
        const float a02 =  2.0f * cx / (float)RR_W - 1.0f;
        const float a10 =  (w / (float)RR_W) * ss;
        const float a11 =  (h / (float)RR_H) * cc;
        const float a12 =  2.0f * cy / (float)RR_H - 1.0f;

        const int oy = tid / OUT_W;
        const int ox = tid - oy * OUT_W;
        const float xs = (2.0f * (float)ox + 1.0f) / (float)OUT_W - 1.0f;
        const float ys = (2.0f * (float)oy + 1.0f) / (float)OUT_H - 1.0f;

        const float gx = a00 * xs + a01 * ys + a02;
        const float gy = a10 * xs + a11 * ys + a12;

        const float ix = ((gx + 1.0f) * (float)RR_W - 1.0f) * 0.5f;
        const float iy = ((gy + 1.0f) * (float)RR_H - 1.0f) * 0.5f;

        const float x0 = floorf(ix);
        const float y0 = floorf(iy);
        const float wx1 = ix - x0;
        const float wy1 = iy - y0;

        #pragma unroll
        for (int k = 0; k < 4; k++) {
            const float xc = x0 + (float)(k & 1);
            const float yc = y0 + (float)(k >> 1);
            const float wgt = ((k & 1)  ? wx1 : (1.0f - wx1)) *
                              ((k >> 1) ? wy1 : (1.0f - wy1));
            const bool valid = (xc >= 0.0f) && (xc <= (float)(RR_W - 1)) &&
                               (yc >= 0.0f) && (yc <= (float)(RR_H - 1));
            const float xcl = fminf(fmaxf(xc, 0.0f), (float)(RR_W - 1));
            const float ycl = fminf(fmaxf(yc, 0.0f), (float)(RR_H - 1));
            const int xi = (int)xcl;
            const int yi = (int)ycl;
            s_off[k][tid] = (yi * RR_W + xi) * RR_C;
            s_w[k][tid]   = valid ? wgt : 0.0f;
        }
    }
    __syncthreads();

    const int q  = tid & 31;              // slot octet -> channels q+32i
    const int pg = tid >> 5;              // 0..15 point group
    const __half* __restrict__ base =
        g_fm_h + (size_t)b * RR_HW * RR_C + 8 * q;

    #pragma unroll
    for (int j = 0; j < 4; j++) {
        const int p  = 16 * j + pg;
        const int pi = min(p, NPTS - 1);

        const uint4 u0 = *(const uint4*)(base + s_off[0][pi]);
        const uint4 u1 = *(const uint4*)(base + s_off[1][pi]);
        const uint4 u2 = *(const uint4*)(base + s_off[2][pi]);
        const uint4 u3 = *(const uint4*)(base + s_off[3][pi]);

        const __half2 W0 = __float2half2_rn(s_w[0][pi]);
        const __half2 W1 = __float2half2_rn(s_w[1][pi]);
        const __half2 W2 = __float2half2_rn(s_w[2][pi]);
        const __half2 W3 = __float2half2_rn(s_w[3][pi]);

        // half2 4-corner accumulation; pairs = channels (q+64m, q+32+64m)
        __half2 h0 = __hmul2(W0, *(const __half2*)&u0.x);
        h0 = __hfma2(W1, *(const __half2*)&u1.x, h0);
        h0 = __hfma2(W2, *(const __half2*)&u2.x, h0);
        h0 = __hfma2(W3, *(const __half2*)&u3.x, h0);

        __half2 h1 = __hmul2(W0, *(const __half2*)&u0.y);
        h1 = __hfma2(W1, *(const __half2*)&u1.y, h1);
        h1 = __hfma2(W2, *(const __half2*)&u2.y, h1);
        h1 = __hfma2(W3, *(const __half2*)&u3.y, h1);

        __half2 h2 = __hmul2(W0, *(const __half2*)&u0.z);
        h2 = __hfma2(W1, *(const __half2*)&u1.z, h2);
        h2 = __hfma2(W2, *(const __half2*)&u2.z, h2);
        h2 = __hfma2(W3, *(const __half2*)&u3.z, h2);

        __half2 h3 = __hmul2(W0, *(const __half2*)&u0.w);
        h3 = __hfma2(W1, *(const __half2*)&u1.w, h3);
        h3 = __hfma2(W2, *(const __half2*)&u2.w, h3);
        h3 = __hfma2(W3, *(const __half2*)&u3.w, h3);

        if (p < NPTS) {
            const float2 f0 = __half22float2(h0);
            const float2 f1 = __half22float2(h1);
            const float2 f2 = __half22float2(h2);
            const float2 f3 = __half22float2(h3);
            // slot 8q+i is channel 32i+q; lane delta = 49 words (odd)
            // -> conflict-free scalar STS
            s_out[(q       ) * NPTS + p] = f0.x;
            s_out[(q + 32  ) * NPTS + p] = f0.y;
            s_out[(q + 64  ) * NPTS + p] = f1.x;
            s_out[(q + 96  ) * NPTS + p] = f1.y;
            s_out[(q + 128 ) * NPTS + p] = f2.x;
            s_out[(q + 160 ) * NPTS + p] = f2.y;
            s_out[(q + 192 ) * NPTS + p] = f3.x;
            s_out[(q + 224 ) * NPTS + p] = f3.y;
        }
    }
    __syncthreads();

    // Bulk async epilogue: one 50176B smem -> gmem copy (TMA engine) with an
    // evict_first L2 policy so the out lines don't linger dirty in L2 and
    // penalize the next replay's transpose.
    if (tid == 0) {
        float* dst = out + (size_t)bn * RR_C * NPTS;
        uint32_t saddr;
        asm volatile("{ .reg .u64 t; cvta.to.shared.u64 t, %1; cvt.u32.u64 %0, t; }"
                     : "=r"(saddr) : "l"(s_out));
        uint64_t pol;
        asm volatile("createpolicy.fractional.L2::evict_first.b64 %0, 1.0;"
                     : "=l"(pol));
        asm volatile("fence.proxy.async.shared::cta;" ::: "memory");
        asm volatile("cp.async.bulk.global.shared::cta.bulk_group.L2::cache_hint "
                     "[%0], [%1], %2, %3;"
                     :: "l"(dst), "r"(saddr), "n"(OUT_BYTES), "l"(pol) : "memory");
        asm volatile("cp.async.bulk.commit_group;" ::: "memory");
        asm volatile("cp.async.bulk.wait_group.read 0;" ::: "memory");
    }
}

// ---------------------------------------------------------------------------

extern "C" void kernel_launch(void* const* d_in, const int* in_sizes, int n_in,
                              void* d_out, int out_size)
{
    const float* fm    = (const float*)d_in[0];
    const float* boxes = (const float*)d_in[1];
    float* out         = (float*)d_out;

    static int smem_set = 0;
    if (!smem_set) {
        cudaFuncSetAttribute(rroi_sample_kernel,
                             cudaFuncAttributeMaxDynamicSharedMemorySize,
                             RR_C * NPTS * (int)sizeof(float));
        smem_set = 1;
    }

    dim3 tgrid(RR_HW / 128, RR_C / 32, RR_B);
    rroi_transpose_kernel<<<tgrid, 256>>>(fm);

    rroi_sample_kernel<<<RR_B * RR_N, 512, RR_C * NPTS * (int)sizeof(float)>>>(boxes, out);
}